// round 7
// baseline (speedup 1.0000x reference)
#include <cuda_runtime.h>
#include <cuda_bf16.h>
#include <cstdint>

// Retrace loss via suffix scan of affine transforms.
// cp.async ping-pong staging (static 41KB smem) + SERIAL-CHUNK scan:
//   thread t owns contiguous elements [4t, 4t+4): serial compose (FMA) ->
//   one 32-lane warp suffix scan of thread aggregates (10 SHFL) ->
//   value-space serial fold of the 8 warp aggregates (no 2nd scan phase).
// Fast division (__fdividef). 2 barriers/row.
//
//   j < 1023:  b[j] = g*clip(tp[j+2]/bp[j+2], eps, 1)
//              a[j] = rw[j+1] + g*eQ[j+2] - b[j]*tQ[j+2]
//   j == 1023: identity (0,1)
//   Q_ret[j] = a[j] + b[j]*Q_ret[j+1],  Q_ret past end = Q[1024]
//   out = mean (Q[j]-Q_ret[j])^2 over (4096,1024)
//
// Row stride 1025 floats => row r base has float alignment shift = r & 3.
// Staged arrays copy the 16B-aligned superset [base-shift, +1028) and are
// read at +shift. Row 4095 (shift=3) ends exactly at the array end.

#define GAMMA  0.99f
#define TLEN   1024
#define STRIDE 1025
#define RPB    8
#define APAD   1028
#define NARR   5                       // staged: eQ,tQ,rw,tp,bp
#define STAGE_FLOATS (NARR * APAD)

__global__ void zero_out_kernel(float* out) { out[0] = 0.0f; }

__device__ __forceinline__ void cp16(uint32_t saddr, const float* g) {
    asm volatile("cp.async.cg.shared.global [%0], [%1], 16;"
                 :: "r"(saddr), "l"(g));
}
__device__ __forceinline__ void cp_commit() {
    asm volatile("cp.async.commit_group;");
}
__device__ __forceinline__ void cp_wait1() {
    asm volatile("cp.async.wait_group 1;");
}
__device__ __forceinline__ void cp_wait0() {
    asm volatile("cp.async.wait_group 0;");
}

__global__ __launch_bounds__(256)
void retrace_kernel(const float* __restrict__ Q,
                    const float* __restrict__ eQ,
                    const float* __restrict__ tQ,
                    const float* __restrict__ rw,
                    const float* __restrict__ tp,
                    const float* __restrict__ bp,
                    float* __restrict__ out,
                    int B) {
    __shared__ __align__(16) float sbuf[2][STAGE_FLOATS];  // 41120 B
    __shared__ float wAg[8], wBg[8];   // warp aggregates
    __shared__ float red[8];

    const int t    = threadIdx.x;
    const int lane = t & 31;
    const int warp = t >> 5;           // 0..7
    const int row0 = blockIdx.x * RPB;

    // ---- issue one row's async copies into stage p (16B aligned vec4) ----
    auto issue_row = [&](int row, int p) {
        const int  shift = row & 3;
        const long gal   = (long)row * STRIDE - shift;   // 16B-aligned index
        float* stage = sbuf[p];
        #pragma unroll
        for (int arr = 0; arr < NARR; arr++) {
            const float* src =
                (arr == 0 ? eQ : arr == 1 ? tQ : arr == 2 ? rw :
                 arr == 3 ? tp : bp) + gal;
            float* dst = stage + arr * APAD;
            cp16((uint32_t)__cvta_generic_to_shared(dst + 4 * t), src + 4 * t);
            if (t == 0)
                cp16((uint32_t)__cvta_generic_to_shared(dst + 4 * 256),
                     src + 4 * 256);
        }
        cp_commit();
    };

    float sq = 0.0f;

    issue_row(row0, 0);                // prologue

    #pragma unroll 1
    for (int i = 0; i < RPB; i++) {
        const int  p     = i & 1;
        const int  row   = row0 + i;
        const int  shift = row & 3;
        const long gb    = (long)row * STRIDE;

        if (i + 1 < RPB) { issue_row(row + 1, p ^ 1); cp_wait1(); }
        else             { cp_wait0(); }
        __syncthreads();               // barrier 1: stage p visible

        // Q direct from gmem: thread t reads its contiguous chunk
        float Qv[4];
        #pragma unroll
        for (int e = 0; e < 4; e++)
            Qv[e] = Q[gb + 4 * t + e];
        const float ql = __ldg(&Q[gb + TLEN]);

        const float* bE = sbuf[p] + shift;
        const float* bT = bE + APAD;
        const float* bR = bE + 2 * APAD;
        const float* bP = bE + 3 * APAD;
        const float* bB = bE + 4 * APAD;

        // ---- per-element transforms (fast division) ----
        float ae[4], be[4];
        #pragma unroll
        for (int e = 0; e < 4; e++) {
            const int j = 4 * t + e;
            if (j < TLEN - 1) {
                float c = __fdividef(bP[j + 2], bB[j + 2]);
                c = fminf(fmaxf(c, 1e-10f), 1.0f);
                be[e] = GAMMA * c;
                ae[e] = fmaf(GAMMA, bE[j + 2], bR[j + 1]) - be[e] * bT[j + 2];
            } else {                   // j == 1023: identity
                ae[e] = 0.0f;
                be[e] = 1.0f;
            }
        }

        // ---- serial compose of the thread chunk (suffix transform) ----
        float A = ae[3], Bv = be[3];
        #pragma unroll
        for (int e = 2; e >= 0; e--) {
            A  = fmaf(be[e], A, ae[e]);
            Bv = be[e] * Bv;
        }

        // ---- warp inclusive suffix scan of thread aggregates ----
        float iA = A, iB = Bv;
        #pragma unroll
        for (int d = 1; d < 32; d <<= 1) {
            float oA = __shfl_down_sync(0xffffffffu, iA, d);
            float oB = __shfl_down_sync(0xffffffffu, iB, d);
            if (lane + d < 32) {
                iA = fmaf(iB, oA, iA);
                iB = iB * oB;
            }
        }
        // exclusive suffix for this thread (lanes strictly right)
        float eA = __shfl_down_sync(0xffffffffu, iA, 1);
        float eB = __shfl_down_sync(0xffffffffu, iB, 1);
        if (lane == 31) { eA = 0.0f; eB = 1.0f; }

        if (lane == 0) { wAg[warp] = iA; wBg[warp] = iB; }
        __syncthreads();               // barrier 2: aggregates visible

        // ---- value-space fold of warps to the right (uniform per warp) ----
        float x = ql;
        for (int k = 7; k > warp; k--)
            x = fmaf(wBg[k], x, wAg[k]);   // broadcast LDS, no conflicts
        x = fmaf(eB, x, eA);               // value at right edge of chunk

        // ---- apply serially within chunk + accumulate squared error ----
        #pragma unroll
        for (int e = 3; e >= 0; e--) {
            x = fmaf(be[e], x, ae[e]);     // Q_ret[4t+e]
            const float d = Qv[e] - x;
            sq = fmaf(d, d, sq);
        }
        // stage p reads all happened before barrier 2; overwrite at i+1 top
        // is ordered behind it, so no extra barrier needed here.
    }

    // ---- one block reduction for all rows ----
    #pragma unroll
    for (int d = 16; d > 0; d >>= 1)
        sq += __shfl_xor_sync(0xffffffffu, sq, d);

    if (lane == 0) red[warp] = sq;
    __syncthreads();
    if (warp == 0) {
        float v = (lane < 8) ? red[lane] : 0.0f;
        #pragma unroll
        for (int d = 4; d > 0; d >>= 1)
            v += __shfl_xor_sync(0xffffffffu, v, d);
        if (lane == 0)
            atomicAdd(out, v * (1.0f / ((float)B * (float)TLEN)));
    }
}

extern "C" void kernel_launch(void* const* d_in, const int* in_sizes, int n_in,
                              void* d_out, int out_size) {
    const float* Q  = (const float*)d_in[0];
    const float* eQ = (const float*)d_in[1];
    const float* tQ = (const float*)d_in[2];
    const float* rw = (const float*)d_in[3];
    const float* tp = (const float*)d_in[4];
    const float* bp = (const float*)d_in[5];
    float* out = (float*)d_out;

    const int B    = in_sizes[0] / STRIDE;   // 4096
    const int grid = B / RPB;                // 512

    zero_out_kernel<<<1, 1>>>(out);
    retrace_kernel<<<grid, 256>>>(Q, eQ, tQ, rw, tp, bp, out, B);
}

// round 9
// speedup vs baseline: 1.0781x; 1.0781x over previous
#include <cuda_runtime.h>
#include <cuda_bf16.h>
#include <cstdint>

// Retrace loss via suffix scan of affine transforms.
// TMA bulk (cp.async.bulk + mbarrier) ping-pong staging: 5 bulk copies per
// row issued by one thread replace ~1285 per-thread LDGSTS, bypassing the
// LSU-issue ceiling that pinned DRAM at ~48% in rounds 2-7.
//
// FIX vs R8: fence.proxy.async.shared::cta after mbarrier init, before any
// TMA use — generic-proxy init must be made visible to the async proxy or
// complete_tx can be lost (hang -> container timeout).
//
//   j < 1023:  b[j] = g*clip(tp[j+2]/bp[j+2], eps, 1)
//              a[j] = rw[j+1] + g*eQ[j+2] - b[j]*tQ[j+2]
//   j == 1023: identity (0,1)
//   Q_ret[j] = a[j] + b[j]*Q_ret[j+1],  Q_ret past end = Q[1024]
//   out = mean (Q[j]-Q_ret[j])^2 over (4096,1024)
//
// Row stride 1025 floats => row r base has float alignment shift = r & 3.
// Each staged array bulk-copies the 16B-aligned superset [base-shift, +1028)
// (4112 B) and is read at +shift. Row 4095 (shift=3) ends exactly at the
// array end -> no OOB.
//
// 256 threads/CTA, RPB=8, grid=512 (single wave). Static smem ~41.3KB.

#define GAMMA  0.99f
#define TLEN   1024
#define STRIDE 1025
#define RPB    8
#define APAD   1028
#define NARR   5                         // staged: eQ,tQ,rw,tp,bp
#define STAGE_FLOATS (NARR * APAD)
#define ROW_TX_BYTES (NARR * APAD * 4)   // 20560

__global__ void zero_out_kernel(float* out) { out[0] = 0.0f; }

__device__ __forceinline__ void mbar_init(uint32_t addr, uint32_t count) {
    asm volatile("mbarrier.init.shared.b64 [%0], %1;" :: "r"(addr), "r"(count)
                 : "memory");
}
__device__ __forceinline__ void fence_proxy_async_shared() {
    asm volatile("fence.proxy.async.shared::cta;" ::: "memory");
}
__device__ __forceinline__ void mbar_expect_tx(uint32_t addr, uint32_t bytes) {
    asm volatile("mbarrier.arrive.expect_tx.shared.b64 _, [%0], %1;"
                 :: "r"(addr), "r"(bytes) : "memory");
}
__device__ __forceinline__ void mbar_wait(uint32_t addr, uint32_t parity) {
    uint32_t done;
    asm volatile(
        "{\n\t"
        ".reg .pred p;\n\t"
        "mbarrier.try_wait.parity.acquire.cta.shared::cta.b64 p, [%1], %2;\n\t"
        "selp.b32 %0, 1, 0, p;\n\t"
        "}"
        : "=r"(done) : "r"(addr), "r"(parity) : "memory");
    if (!done) {
        asm volatile(
            "{\n\t"
            ".reg .pred P1;\n\t"
            "WAIT_LOOP_%=:\n\t"
            "mbarrier.try_wait.parity.acquire.cta.shared::cta.b64 P1, [%0], %1, 0x989680;\n\t"
            "@P1 bra.uni WAIT_DONE_%=;\n\t"
            "bra.uni WAIT_LOOP_%=;\n\t"
            "WAIT_DONE_%=:\n\t"
            "}"
            :: "r"(addr), "r"(parity) : "memory");
    }
}
__device__ __forceinline__ void bulk_cp(uint32_t sdst, const float* gsrc,
                                        uint32_t bytes, uint32_t mbar) {
    asm volatile(
        "cp.async.bulk.shared::cta.global.mbarrier::complete_tx::bytes "
        "[%0], [%1], %2, [%3];"
        :: "r"(sdst), "l"(gsrc), "r"(bytes), "r"(mbar) : "memory");
}

__global__ __launch_bounds__(256)
void retrace_kernel(const float* __restrict__ Q,
                    const float* __restrict__ eQ,
                    const float* __restrict__ tQ,
                    const float* __restrict__ rw,
                    const float* __restrict__ tp,
                    const float* __restrict__ bp,
                    float* __restrict__ out,
                    int B) {
    __shared__ __align__(16) float sbuf[2][STAGE_FLOATS];   // 41120 B
    __shared__ __align__(8) unsigned long long mbar_store[2];
    __shared__ float wAg[8], wBg[8];
    __shared__ float red[8];

    const int t    = threadIdx.x;
    const int lane = t & 31;
    const int warp = t >> 5;             // 0..7
    const int row0 = blockIdx.x * RPB;

    const uint32_t mb0 = (uint32_t)__cvta_generic_to_shared(&mbar_store[0]);
    const uint32_t mb1 = (uint32_t)__cvta_generic_to_shared(&mbar_store[1]);

    if (t == 0) {
        mbar_init(mb0, 1);
        mbar_init(mb1, 1);
        fence_proxy_async_shared();      // init visible to async proxy
    }
    __syncthreads();                     // barriers visible CTA-wide

    // ---- issue one row's bulk copies into stage p (thread 0 only) ----
    auto issue_row = [&](int row, int p) {
        if (t != 0) return;
        const int  shift = row & 3;
        const long gal   = (long)row * STRIDE - shift;    // 16B-aligned index
        const uint32_t mb = p ? mb1 : mb0;
        mbar_expect_tx(mb, ROW_TX_BYTES);
        float* stage = sbuf[p];
        const float* srcs[NARR] = { eQ + gal, tQ + gal, rw + gal,
                                    tp + gal, bp + gal };
        #pragma unroll
        for (int arr = 0; arr < NARR; arr++) {
            uint32_t sdst =
                (uint32_t)__cvta_generic_to_shared(stage + arr * APAD);
            bulk_cp(sdst, srcs[arr], APAD * 4, mb);
        }
    };

    float sq = 0.0f;

    issue_row(row0, 0);                  // prologue

    #pragma unroll 1
    for (int i = 0; i < RPB; i++) {
        const int  p      = i & 1;
        const int  parity = (i >> 1) & 1;
        const int  row    = row0 + i;
        const int  shift  = row & 3;
        const long gb     = (long)row * STRIDE;

        if (i + 1 < RPB) issue_row(row + 1, p ^ 1);

        mbar_wait(p ? mb1 : mb0, parity);   // stage p data + acquire

        // Q direct from gmem (contiguous per-thread chunk; hidden by scan)
        float Qv[4];
        #pragma unroll
        for (int e = 0; e < 4; e++)
            Qv[e] = Q[gb + 4 * t + e];
        const float ql = __ldg(&Q[gb + TLEN]);

        const float* bE = sbuf[p] + shift;
        const float* bT = bE + APAD;
        const float* bR = bE + 2 * APAD;
        const float* bP = bE + 3 * APAD;
        const float* bB = bE + 4 * APAD;

        // ---- per-element transforms (fast division) ----
        float ae[4], be[4];
        #pragma unroll
        for (int e = 0; e < 4; e++) {
            const int j = 4 * t + e;
            if (j < TLEN - 1) {
                float c = __fdividef(bP[j + 2], bB[j + 2]);
                c = fminf(fmaxf(c, 1e-10f), 1.0f);
                be[e] = GAMMA * c;
                ae[e] = fmaf(GAMMA, bE[j + 2], bR[j + 1]) - be[e] * bT[j + 2];
            } else {                     // j == 1023: identity
                ae[e] = 0.0f;
                be[e] = 1.0f;
            }
        }

        // ---- serial compose of the thread chunk (suffix transform) ----
        float A = ae[3], Bv = be[3];
        #pragma unroll
        for (int e = 2; e >= 0; e--) {
            A  = fmaf(be[e], A, ae[e]);
            Bv = be[e] * Bv;
        }

        // ---- warp inclusive suffix scan of thread aggregates ----
        float iA = A, iB = Bv;
        #pragma unroll
        for (int d = 1; d < 32; d <<= 1) {
            float oA = __shfl_down_sync(0xffffffffu, iA, d);
            float oB = __shfl_down_sync(0xffffffffu, iB, d);
            if (lane + d < 32) {
                iA = fmaf(iB, oA, iA);
                iB = iB * oB;
            }
        }
        float eA = __shfl_down_sync(0xffffffffu, iA, 1);
        float eB = __shfl_down_sync(0xffffffffu, iB, 1);
        if (lane == 31) { eA = 0.0f; eB = 1.0f; }

        if (lane == 0) { wAg[warp] = iA; wBg[warp] = iB; }
        __syncthreads();                 // aggregates visible

        // ---- value-space fold of warps to the right (uniform per warp) ----
        float x = ql;
        for (int k = 7; k > warp; k--)
            x = fmaf(wBg[k], x, wAg[k]); // broadcast LDS
        x = fmaf(eB, x, eA);             // value at right edge of chunk

        // ---- apply serially within chunk + accumulate squared error ----
        #pragma unroll
        for (int e = 3; e >= 0; e--) {
            x = fmaf(be[e], x, ae[e]);   // Q_ret[4t+e]
            const float d = Qv[e] - x;
            sq = fmaf(d, d, sq);
        }
        __syncthreads();                 // stage p reads done before its reuse
    }

    // ---- one block reduction for all rows ----
    #pragma unroll
    for (int d = 16; d > 0; d >>= 1)
        sq += __shfl_xor_sync(0xffffffffu, sq, d);

    if (lane == 0) red[warp] = sq;
    __syncthreads();
    if (warp == 0) {
        float v = (lane < 8) ? red[lane] : 0.0f;
        #pragma unroll
        for (int d = 4; d > 0; d >>= 1)
            v += __shfl_xor_sync(0xffffffffu, v, d);
        if (lane == 0)
            atomicAdd(out, v * (1.0f / ((float)B * (float)TLEN)));
    }
}

extern "C" void kernel_launch(void* const* d_in, const int* in_sizes, int n_in,
                              void* d_out, int out_size) {
    const float* Q  = (const float*)d_in[0];
    const float* eQ = (const float*)d_in[1];
    const float* tQ = (const float*)d_in[2];
    const float* rw = (const float*)d_in[3];
    const float* tp = (const float*)d_in[4];
    const float* bp = (const float*)d_in[5];
    float* out = (float*)d_out;

    const int B    = in_sizes[0] / STRIDE;   // 4096
    const int grid = B / RPB;                // 512

    zero_out_kernel<<<1, 1>>>(out);
    retrace_kernel<<<grid, 256>>>(Q, eQ, tQ, rw, tp, bp, out, B);
}